// round 16
// baseline (speedup 1.0000x reference)
#include <cuda_runtime.h>
#include <cuda_bf16.h>
#include <cstdint>

// Problem constants
#define CDIM 32
#define HDIM 3200
#define BDIM 1024
#define RDIM 500
#define KDIM 30
#define N2_DIM 1030
#define NITER 200
#define KSPLIT 4
#define PSTRIDE 512
#define ADMM_EPS 1.5e-3f
#define ALPHA 1.6f   // ADMM over-relaxation (fixed point unchanged)

// ---------------------------------------------------------------------------
// Device-global scratch (no allocation allowed)
// ---------------------------------------------------------------------------
__device__ __nv_bfloat16 g_dh[BDIM * CDIM],  g_dl[BDIM * CDIM];
__device__ __nv_bfloat16 g_W1h[HDIM * CDIM], g_W1l[HDIM * CDIM];
__device__ __nv_bfloat16 g_W2h[HDIM * HDIM], g_W2l[HDIM * HDIM];
__device__ __nv_bfloat16 g_W3h[RDIM * HDIM], g_W3l[RDIM * HDIM];
__device__ __nv_bfloat16 g_h1h[BDIM * HDIM], g_h1l[BDIM * HDIM];
__device__ __nv_bfloat16 g_h2h[BDIM * HDIM], g_h2l[BDIM * HDIM];
__device__ float g_costP[KSPLIT * BDIM * PSTRIDE];
__device__ float g_Sinv[KDIM * KDIM];

// ---------------------------------------------------------------------------
// PTX helpers (plain sm_80+/sm_100 base features — no arch-'a' gated instrs)
// ---------------------------------------------------------------------------
__device__ __forceinline__ uint32_t smem_u32(const void* p) {
  uint32_t a;
  asm("{ .reg .u64 t; cvta.to.shared.u64 t, %1; cvt.u32.u64 %0, t; }" : "=r"(a) : "l"(p));
  return a;
}
__device__ __forceinline__ void ldsm4(uint32_t* r, uint32_t a) {
  asm volatile("ldmatrix.sync.aligned.m8n8.x4.shared.b16 {%0,%1,%2,%3}, [%4];"
               : "=r"(r[0]), "=r"(r[1]), "=r"(r[2]), "=r"(r[3]) : "r"(a));
}
__device__ __forceinline__ void mma16816(float* c, const uint32_t* a, const uint32_t* b) {
  asm volatile(
      "mma.sync.aligned.m16n8k16.row.col.f32.bf16.bf16.f32 "
      "{%0,%1,%2,%3}, {%4,%5,%6,%7}, {%8,%9}, {%0,%1,%2,%3};"
      : "+f"(c[0]), "+f"(c[1]), "+f"(c[2]), "+f"(c[3])
      : "r"(a[0]), "r"(a[1]), "r"(a[2]), "r"(a[3]), "r"(b[0]), "r"(b[1]));
}
#define CP_COMMIT() asm volatile("cp.async.commit_group;" ::: "memory")
#define CP_WAIT(n)  asm volatile("cp.async.wait_group %0;" :: "n"(n) : "memory")

// Packed fp32x2 (Blackwell FFMA2 path; base PTX, sm_100+)
__device__ __forceinline__ unsigned long long ffma2(unsigned long long a, unsigned long long b,
                                                    unsigned long long c) {
  unsigned long long d;
  asm("fma.rn.f32x2 %0, %1, %2, %3;" : "=l"(d) : "l"(a), "l"(b), "l"(c));
  return d;
}
__device__ __forceinline__ unsigned long long fadd2(unsigned long long a, unsigned long long b) {
  unsigned long long d;
  asm("add.rn.f32x2 %0, %1, %2;" : "=l"(d) : "l"(a), "l"(b));
  return d;
}
__device__ __forceinline__ void lds_v2b64(unsigned long long& a, unsigned long long& b, uint32_t addr) {
  asm volatile("ld.shared.v2.b64 {%0,%1}, [%2];" : "=l"(a), "=l"(b) : "r"(addr));
}
__device__ __forceinline__ float2 unpack2(unsigned long long v) {
  float2 f;
  asm("mov.b64 {%0,%1}, %2;" : "=f"(f.x), "=f"(f.y) : "l"(v));
  return f;
}
__device__ __forceinline__ unsigned long long pack2(float x, float y) {
  unsigned long long v;
  asm("mov.b64 %0, {%1,%2};" : "=l"(v) : "f"(x), "f"(y));
  return v;
}

// SW64 swizzle for 64-byte rows (conflict-free ldmatrix over 8-row atoms)
__device__ __forceinline__ uint32_t sw64(uint32_t bo) { return bo ^ ((bo >> 3) & 0x30); }

// ---------------------------------------------------------------------------
// Fused fp32 -> (bf16 hi, bf16 lo) split; 4 x float4 per thread (MLP=4).
// Counts below are in float4 QUADS (16 floats).
// ---------------------------------------------------------------------------
#define CVT_Q_D   2048
#define CVT_Q_W1  6400
#define CVT_Q_W2  640000
#define CVT_Q_W3  100000
#define CVT_Q1 (CVT_Q_D)
#define CVT_Q2 (CVT_Q1 + CVT_Q_W1)
#define CVT_Q3 (CVT_Q2 + CVT_Q_W2)
#define CVT_Q4 (CVT_Q3 + CVT_Q_W3)

__device__ __forceinline__ void cvt_one(float4 v, uint2& phv, uint2& plv) {
  __nv_bfloat16 h0 = __float2bfloat16_rn(v.x), h1 = __float2bfloat16_rn(v.y);
  __nv_bfloat16 h2 = __float2bfloat16_rn(v.z), h3 = __float2bfloat16_rn(v.w);
  __nv_bfloat16 l0 = __float2bfloat16_rn(v.x - __bfloat162float(h0));
  __nv_bfloat16 l1 = __float2bfloat16_rn(v.y - __bfloat162float(h1));
  __nv_bfloat16 l2 = __float2bfloat16_rn(v.z - __bfloat162float(h2));
  __nv_bfloat16 l3 = __float2bfloat16_rn(v.w - __bfloat162float(h3));
  phv.x = ((uint32_t)__bfloat16_as_ushort(h1) << 16) | __bfloat16_as_ushort(h0);
  phv.y = ((uint32_t)__bfloat16_as_ushort(h3) << 16) | __bfloat16_as_ushort(h2);
  plv.x = ((uint32_t)__bfloat16_as_ushort(l1) << 16) | __bfloat16_as_ushort(l0);
  plv.y = ((uint32_t)__bfloat16_as_ushort(l3) << 16) | __bfloat16_as_ushort(l2);
}

__global__ void cvt_all(const float* __restrict__ d, const float* __restrict__ W1,
                        const float* __restrict__ W2, const float* __restrict__ W3,
                        __nv_bfloat16* dh, __nv_bfloat16* dl,
                        __nv_bfloat16* w1h, __nv_bfloat16* w1l,
                        __nv_bfloat16* w2h, __nv_bfloat16* w2l,
                        __nv_bfloat16* w3h, __nv_bfloat16* w3l) {
  int i = blockIdx.x * 256 + threadIdx.x;
  const float* src;
  __nv_bfloat16 *ph, *pl;
  int off;
  if (i < CVT_Q1)      { src = d;  ph = dh;  pl = dl;  off = i; }
  else if (i < CVT_Q2) { src = W1; ph = w1h; pl = w1l; off = i - CVT_Q1; }
  else if (i < CVT_Q3) { src = W2; ph = w2h; pl = w2l; off = i - CVT_Q2; }
  else if (i < CVT_Q4) { src = W3; ph = w3h; pl = w3l; off = i - CVT_Q3; }
  else return;
  float4 v[4];
#pragma unroll
  for (int q = 0; q < 4; q++) v[q] = reinterpret_cast<const float4*>(src)[4 * off + q];
  uint2 phv[4], plv[4];
#pragma unroll
  for (int q = 0; q < 4; q++) cvt_one(v[q], phv[q], plv[q]);
#pragma unroll
  for (int q = 0; q < 4; q++) {
    reinterpret_cast<uint2*>(ph)[4 * off + q] = phv[q];
    reinterpret_cast<uint2*>(pl)[4 * off + q] = plv[q];
  }
}

// ---------------------------------------------------------------------------
// Async tile loader: ROWS x 32 bf16 (64 B/row), SW64 swizzle, cp.async 16B.
// ---------------------------------------------------------------------------
template <int ROWS, int NTH>
__device__ __forceinline__ void load_tile_async(uint32_t tile, const __nv_bfloat16* __restrict__ g,
                                                int row0, int rmax, int ldk, int k0, int kend,
                                                int tid) {
  constexpr int NV = ROWS * 4;     // 16B vectors per tile
#pragma unroll
  for (int t = 0; t < NV / NTH; t++) {
    int v = tid + t * NTH;
    int r = v >> 2;                 // tile row
    int cs = v & 3;                 // 16B segment (4 per 64B row)
    int gr = row0 + r;
    int gk = k0 + cs * 8;
    uint32_t dst = tile + sw64(((uint32_t)r << 6) + ((uint32_t)cs << 4));
    if (gr < rmax && gk < kend) {
      const void* src = g + (size_t)gr * ldk + gk;
      asm volatile("cp.async.cg.shared.global [%0], [%1], 16;" :: "r"(dst), "l"(src));
    } else {
      asm volatile("st.shared.v4.b32 [%0], {%1,%1,%1,%1};" :: "r"(dst), "r"(0u));
    }
  }
}

// ---------------------------------------------------------------------------
// bf16x3 split GEMM via mma.sync m16n8k16 (unchanged from R15 passing version).
// Tile 64M x 128N, BK=32, 3-stage cp.async, ONE barrier per chunk.
// 128 threads = 4 warps (2 warp_m x 2 warp_n); warp tile 32M x 64N. 3 CTA/SM.
// MODE 0: full-K, bias+lrelu, emit bf16 hi/lo. MODE 1: split-K fp32 partials.
// ---------------------------------------------------------------------------
#define STAGE_B 24576  // Ah 4KB | Al 4KB | Bh 8KB | Bl 8KB

template <int MODE>
__global__ __launch_bounds__(128, 3)
void mma_gemm(const __nv_bfloat16* __restrict__ Ah, const __nv_bfloat16* __restrict__ Al,
              const __nv_bfloat16* __restrict__ Bh, const __nv_bfloat16* __restrict__ Bl,
              const float* __restrict__ bias, float* __restrict__ Pf,
              __nv_bfloat16* __restrict__ Ch, __nv_bfloat16* __restrict__ Cl,
              int M, int N, int K, int kchunk) {
  extern __shared__ char smem[];
  const uint32_t sb = smem_u32(smem);
  const int tid = threadIdx.x, wid = tid >> 5, lane = tid & 31;
  const int m0 = blockIdx.y * 64, n0 = blockIdx.x * 128;
  const int warp_m = wid & 1;    // 2 x 32 rows
  const int warp_n = wid >> 1;   // 2 x 64 cols

  const int kbeg = (MODE == 1) ? blockIdx.z * kchunk : 0;
  const int kend = (kbeg + kchunk < K) ? (kbeg + kchunk) : K;
  const int NC = (kend - kbeg + 31) / 32;

  float acc[2][4][2][4];
#pragma unroll
  for (int mt = 0; mt < 2; mt++)
#pragma unroll
    for (int g2 = 0; g2 < 4; g2++)
#pragma unroll
      for (int n2 = 0; n2 < 2; n2++)
#pragma unroll
        for (int i = 0; i < 4; i++) acc[mt][g2][n2][i] = 0.f;

#pragma unroll
  for (int s = 0; s < 2; s++) {
    if (s == 1 && NC < 2) break;
    uint32_t tb = sb + s * STAGE_B;
    int k0 = kbeg + s * 32;
    load_tile_async<64, 128>(tb + 0,      Ah, m0, M, K, k0, kend, tid);
    load_tile_async<64, 128>(tb + 4096,   Al, m0, M, K, k0, kend, tid);
    load_tile_async<128, 128>(tb + 8192,  Bh, n0, N, K, k0, kend, tid);
    load_tile_async<128, 128>(tb + 16384, Bl, n0, N, K, k0, kend, tid);
    CP_COMMIT();
  }

  const int a_r = (lane & 15);
  const uint32_t a_koff = (lane & 16) ? 16u : 0u;
  const int b_r = ((lane & 16) ? 8 : 0) + (lane & 7);
  const uint32_t b_koff = (lane & 8) ? 16u : 0u;

  for (int c = 0; c < NC; c++) {
    if (c + 1 < NC) { CP_WAIT(1); } else { CP_WAIT(0); }
    __syncthreads();  // chunk c visible; buf (c-1)%3 reads all complete

    if (c + 2 < NC) {
      uint32_t tb = sb + ((c + 2) % 3) * STAGE_B;
      int k0 = kbeg + (c + 2) * 32;
      load_tile_async<64, 128>(tb + 0,      Ah, m0, M, K, k0, kend, tid);
      load_tile_async<64, 128>(tb + 4096,   Al, m0, M, K, k0, kend, tid);
      load_tile_async<128, 128>(tb + 8192,  Bh, n0, N, K, k0, kend, tid);
      load_tile_async<128, 128>(tb + 16384, Bl, n0, N, K, k0, kend, tid);
      CP_COMMIT();
    }

    const uint32_t tb = sb + (c % 3) * STAGE_B;
#pragma unroll
    for (int ks = 0; ks < 2; ks++) {
      const uint32_t kb = ks * 32;
      uint32_t ah[2][4], al[2][4];
#pragma unroll
      for (int mt = 0; mt < 2; mt++) {
        uint32_t sw = sw64(((uint32_t)(warp_m * 32 + mt * 16 + a_r) << 6) + kb + a_koff);
        ldsm4(ah[mt], tb + sw);
        ldsm4(al[mt], tb + 4096 + sw);
      }
#pragma unroll
      for (int g2 = 0; g2 < 4; g2++) {
        uint32_t bh[4], bl[4];
        uint32_t sw = sw64(((uint32_t)(warp_n * 64 + g2 * 16 + b_r) << 6) + kb + b_koff);
        ldsm4(bh, tb + 8192 + sw);
        ldsm4(bl, tb + 16384 + sw);
#pragma unroll
        for (int mt = 0; mt < 2; mt++) {
#pragma unroll
          for (int n2 = 0; n2 < 2; n2++) {
            mma16816(acc[mt][g2][n2], ah[mt], bh + n2 * 2);
            mma16816(acc[mt][g2][n2], al[mt], bh + n2 * 2);
            mma16816(acc[mt][g2][n2], ah[mt], bl + n2 * 2);
          }
        }
      }
    }
  }

  // Epilogue
#pragma unroll
  for (int mt = 0; mt < 2; mt++) {
#pragma unroll
    for (int g2 = 0; g2 < 4; g2++) {
#pragma unroll
      for (int n2 = 0; n2 < 2; n2++) {
        const int col = n0 + warp_n * 64 + g2 * 16 + n2 * 8 + ((lane & 3) << 1);
        const int r0 = m0 + warp_m * 32 + mt * 16 + (lane >> 2);
#pragma unroll
        for (int h = 0; h < 2; h++) {
          const int row = r0 + h * 8;
          float v0 = acc[mt][g2][n2][h * 2 + 0];
          float v1 = acc[mt][g2][n2][h * 2 + 1];
          if (MODE == 0) {
            if (col < N) {
              v0 += bias[col];
              v1 += bias[col + 1];
              v0 = (v0 > 0.f) ? v0 : 0.1f * v0;
              v1 = (v1 > 0.f) ? v1 : 0.1f * v1;
              __nv_bfloat16 h0 = __float2bfloat16_rn(v0), h1 = __float2bfloat16_rn(v1);
              __nv_bfloat16 l0 = __float2bfloat16_rn(v0 - __bfloat162float(h0));
              __nv_bfloat16 l1 = __float2bfloat16_rn(v1 - __bfloat162float(h1));
              uint32_t ph = ((uint32_t)__bfloat16_as_ushort(h1) << 16) | __bfloat16_as_ushort(h0);
              uint32_t pl = ((uint32_t)__bfloat16_as_ushort(l1) << 16) | __bfloat16_as_ushort(l0);
              *reinterpret_cast<uint32_t*>(Ch + (size_t)row * N + col) = ph;
              *reinterpret_cast<uint32_t*>(Cl + (size_t)row * N + col) = pl;
            }
          } else {
            if (col < PSTRIDE) {
              float* dst = Pf + (size_t)blockIdx.z * BDIM * PSTRIDE + (size_t)row * PSTRIDE + col;
              *reinterpret_cast<float2*>(dst) = make_float2(v0, v1);
            }
          }
        }
      }
    }
  }
}

// ---------------------------------------------------------------------------
// Setup: S = I + 0.5 * W W^T (30x30), invert via Gauss-Jordan. 1024 threads.
// ---------------------------------------------------------------------------
__global__ void setup_sinv(const float* __restrict__ W, float* __restrict__ Sinv) {
  __shared__ float aug[KDIM][64];
  __shared__ float fac[KDIM];
  __shared__ float pivinv;
  const int tid = threadIdx.x;  // 1024 threads

  if (tid < KDIM * KDIM) {
    int a = tid / KDIM, b = tid % KDIM;
    float s = 0.f;
    for (int j = 0; j < RDIM; j++) s += W[a * RDIM + j] * W[b * RDIM + j];
    aug[a][b] = 0.5f * s + (a == b ? 1.f : 0.f);
  }
  for (int idx = tid; idx < KDIM * 34; idx += 1024) {
    int a = idx / 34, c = 30 + idx % 34;
    aug[a][c] = (c - 30 == a) ? 1.f : 0.f;
  }
  __syncthreads();

  for (int i = 0; i < KDIM; i++) {
    if (tid == 0) pivinv = 1.f / aug[i][i];
    __syncthreads();
    if (tid < 64) aug[i][tid] *= pivinv;
    __syncthreads();
    if (tid < KDIM) fac[tid] = aug[tid][i];
    __syncthreads();
    for (int idx = tid; idx < KDIM * 64; idx += 1024) {
      int r = idx / 64, c = idx % 64;
      if (r != i) aug[r][c] -= fac[r] * aug[i][c];
    }
    __syncthreads();
  }
  for (int idx = tid; idx < KDIM * KDIM; idx += 1024)
    Sinv[idx] = aug[idx / KDIM][30 + idx % KDIM];
}

// ---------------------------------------------------------------------------
// Persistent ADMM kernel — 512 threads, 8 rows/block, 128 blocks.
//  * over-relaxation alpha=1.6; deterministic early exit (check every 2 iters)
//  * M1: warps = (row-pair x k-quarter); pr/ps in registers; FFMA2 matvecs
// ---------------------------------------------------------------------------
#define AROWS 8

__global__ __launch_bounds__(512, 1)
void admm_kernel(const float* __restrict__ costP, const float* __restrict__ b3,
                 const float* __restrict__ W, const float* __restrict__ cap,
                 const float* __restrict__ SinvG, float* __restrict__ out) {
  extern __shared__ float sm[];
  float* Ws   = sm;                     // [32][512] (rows 30,31 zero)
  float* ev   = Ws + 32 * 512;          // [8][512]
  float* cst  = ev + AROWS * 512;       // [8][512]
  float* pk   = cst + AROWS * 512;      // [8][32]
  float* gk   = pk + AROWS * 32;        // [8][32]
  float* ts   = gk + AROWS * 32;        // [8][32]
  float* y1s  = ts + AROWS * 32;        // [8][32] (lanes 30,31 stay zero)
  float* tcap = y1s + AROWS * 32;       // [32]
  float* Ssm  = tcap + 32;              // [30][33]
  float* wmax = Ssm + KDIM * 33;        // [24]

  const int tid = threadIdx.x;          // 0..511
  const int lane = tid & 31;
  const int wid = tid >> 5;             // 0..15
  const int row0 = blockIdx.x * AROWS;  // 128 blocks x 8 = 1024 exact
  const int j = tid;

  // ---- init ----
  for (int idx = tid; idx < 32 * 512; idx += 512) {
    int k = idx >> 9, jj = idx & 511;
    Ws[idx] = (k < KDIM && jj < RDIM) ? W[k * RDIM + jj] : 0.f;
  }
#pragma unroll
  for (int r = 0; r < AROWS; r++) {
    float cv = 0.f;
    if (j < RDIM) {
      cv = b3[j];
#pragma unroll
      for (int z = 0; z < KSPLIT; z++)
        cv += costP[(size_t)z * BDIM * PSTRIDE + (size_t)(row0 + r) * PSTRIDE + j];
    }
    cst[r * 512 + j] = cv;
    ev[r * 512 + j] = cv;   // p = 0 -> e = cost
  }
  for (int idx = tid; idx < KDIM * 33; idx += 512) {
    int k = idx / 33, m = idx % 33;
    Ssm[idx] = (m < KDIM) ? SinvG[k * KDIM + m] : 0.f;
  }
  for (int idx = tid; idx < AROWS * 32; idx += 512) {
    pk[idx] = 0.f; gk[idx] = 0.f; ts[idx] = 0.f; y1s[idx] = 0.f;
  }
  if (tid < 24) wmax[tid] = 1e30f;
  __syncthreads();

  // tcap_k = (sum_j W[k][j]) - 2*cap_k
  {
    int k = wid * 2;
#pragma unroll
    for (int q = 0; q < 2; q++, k++) {
      if (k < KDIM) {
        float s = 0.f;
#pragma unroll
        for (int m = 0; m < 16; m++) s += Ws[k * 512 + lane + 32 * m];
#pragma unroll
        for (int o = 16; o > 0; o >>= 1) s += __shfl_down_sync(0xffffffffu, s, o);
        if (lane == 0) tcap[k] = s - 2.f * cap[k];
      }
    }
  }
  __syncthreads();

  // M2 weights: Wr2[kk] = (Ws[2kk][j], Ws[2kk+1][j]) (k up to 31, zero-padded)
  unsigned long long Wr2[16];
#pragma unroll
  for (int kk = 0; kk < 16; kk++)
    Wr2[kk] = pack2(Ws[(2 * kk) * 512 + j], Ws[(2 * kk + 1) * 512 + j]);

  // Per-thread persistent state (owner thread = j)
  float prr[AROWS], psr[AROWS];
#pragma unroll
  for (int r = 0; r < AROWS; r++) { prr[r] = 0.f; psr[r] = 0.f; }

  const int rp = wid & 3;        // row-pair index -> rows 2rp, 2rp+1
  const int kq = wid >> 2;       // k-quarter -> k = 8kq .. 8kq+7
  const int r0m = 2 * rp, r1m = 2 * rp + 1;
  const uint32_t ws_a = smem_u32(Ws);
  const uint32_t ev_a = smem_u32(ev);
  const uint32_t y_a  = smem_u32(y1s);

  bool conv = false;
  for (int it = 0; it < NITER; it++) {
    const bool last = conv || (it == NITER - 1);

    // ---- M1: gk[r][k] = sum_j W[k][j] e[r][j] ----
    {
      unsigned long long e0[8], e1[8];
      const uint32_t eb0 = ev_a + ((uint32_t)(r0m * 512 + lane * 4) << 2);
      const uint32_t eb1 = ev_a + ((uint32_t)(r1m * 512 + lane * 4) << 2);
#pragma unroll
      for (int s = 0; s < 4; s++) {
        lds_v2b64(e0[2 * s], e0[2 * s + 1], eb0 + 512 * s);
        lds_v2b64(e1[2 * s], e1[2 * s + 1], eb1 + 512 * s);
      }
#pragma unroll
      for (int kk = 0; kk < 8; kk++) {
        const int k = kq * 8 + kk;
        const uint32_t wb = ws_a + ((uint32_t)(k * 512 + lane * 4) << 2);
        unsigned long long a00 = 0ull, a01 = 0ull, a10 = 0ull, a11 = 0ull, w0, w1;
#pragma unroll
        for (int s = 0; s < 4; s++) {
          lds_v2b64(w0, w1, wb + 512 * s);
          a00 = ffma2(w0, e0[2 * s], a00);
          a01 = ffma2(w1, e0[2 * s + 1], a01);
          a10 = ffma2(w0, e1[2 * s], a10);
          a11 = ffma2(w1, e1[2 * s + 1], a11);
        }
        float2 f0 = unpack2(fadd2(a00, a01));
        float2 f1 = unpack2(fadd2(a10, a11));
        float v0 = f0.x + f0.y;
        float v1 = f1.x + f1.y;
#pragma unroll
        for (int o = 16; o > 0; o >>= 1) {
          v0 += __shfl_down_sync(0xffffffffu, v0, o);
          v1 += __shfl_down_sync(0xffffffffu, v1, o);
        }
        if (lane == 0) { gk[r0m * 32 + k] = v0; gk[r1m * 32 + k] = v1; }
      }
    }
    __syncthreads();

    // ---- Solve: y1 = Sinv(0.5*gk + |p_k| + tcap); relaxed p_k update ----
    if (wid < AROWS) {
      const int r = wid;
      float pkv = 0.f;
      if (lane < KDIM) {
        pkv = pk[r * 32 + lane];
        ts[r * 32 + lane] = 0.5f * gk[r * 32 + lane] + fabsf(pkv) + tcap[lane];
      }
      __syncwarp(0xffffffffu);
      float dk = 0.f;
      if (lane < KDIM) {
        float y = 0.f;
#pragma unroll
        for (int m = 0; m < KDIM; m++) y += Ssm[lane * 33 + m] * ts[r * 32 + m];
        y1s[r * 32 + lane] = y;
        float xk = 0.5f * (fabsf(pkv) - y);
        float npk = fmaf(ALPHA, xk - fmaxf(pkv, 0.f), pkv);
        pk[r * 32 + lane] = npk;
        dk = fabsf(npk - pkv);
        if (last)
          out[(size_t)(row0 + r) * N2_DIM + RDIM + lane] = xk;
      }
#pragma unroll
      for (int o = 16; o > 0; o >>= 1) dk = fmaxf(dk, __shfl_down_sync(0xffffffffu, dk, o));
      if (lane == 0) wmax[16 + r] = dk;
    }
    __syncthreads();

    // ---- M2+E: wt_j = (W^T y1)_j; relaxed p_r/p_s update; recompute e ----
    float dm = 0.f;
#pragma unroll
    for (int r = 0; r < AROWS; r++) {
      unsigned long long a0 = 0ull, a1 = 0ull, y0, y1v;
      const uint32_t yb = y_a + (uint32_t)(r * 128);
#pragma unroll
      for (int kk8 = 0; kk8 < 8; kk8++) {
        lds_v2b64(y0, y1v, yb + kk8 * 16);
        a0 = ffma2(Wr2[2 * kk8], y0, a0);
        a1 = ffma2(Wr2[2 * kk8 + 1], y1v, a1);
      }
      float2 f = unpack2(fadd2(a0, a1));
      float wt = f.x + f.y;

      float e0 = ev[r * 512 + j];
      float xr = 0.25f * (e0 - wt) + 0.5f;
      float xs = 1.f - xr;
      float np = fmaf(ALPHA, xr - fmaxf(prr[r], 0.f), prr[r]);
      float ns = fmaf(ALPHA, xs - fmaxf(psr[r], 0.f), psr[r]);
      dm = fmaxf(dm, fmaxf(fabsf(np - prr[r]), fabsf(ns - psr[r])));
      prr[r] = np;
      psr[r] = ns;
      ev[r * 512 + j] = cst[r * 512 + j] + fabsf(np) - fabsf(ns);
      if (last && j < RDIM) {
        out[(size_t)(row0 + r) * N2_DIM + j] = xr;
        out[(size_t)(row0 + r) * N2_DIM + RDIM + KDIM + j] = xs;
      }
    }
#pragma unroll
    for (int o = 16; o > 0; o >>= 1) dm = fmaxf(dm, __shfl_down_sync(0xffffffffu, dm, o));
    if (lane == 0) wmax[wid] = dm;
    __syncthreads();

    if (last) break;
    // convergence scan every 2nd iteration (wmax from this iter; uniform)
    if ((it & 1) == 0) {
      float mx = 0.f;
#pragma unroll
      for (int q = 0; q < 24; q++) mx = fmaxf(mx, wmax[q]);
      conv = (mx < ADMM_EPS);
    }
  }
}

// ---------------------------------------------------------------------------
extern "C" void kernel_launch(void* const* d_in, const int* in_sizes, int n_in,
                              void* d_out, int out_size) {
  const float* d   = (const float*)d_in[0];  // [1024,32]
  const float* W1  = (const float*)d_in[1];  // [3200,32]
  const float* b1  = (const float*)d_in[2];  // [3200]
  const float* W2  = (const float*)d_in[3];  // [3200,3200]
  const float* b2  = (const float*)d_in[4];  // [3200]
  const float* W3  = (const float*)d_in[5];  // [500,3200]
  const float* b3  = (const float*)d_in[6];  // [500]
  const float* Wm  = (const float*)d_in[7];  // [30,500]
  const float* cap = (const float*)d_in[8];  // [30]
  float* out = (float*)d_out;                // [1024,1030]

  __nv_bfloat16 *dh, *dl, *w1h, *w1l, *w2h, *w2l, *w3h, *w3l, *h1h, *h1l, *h2h, *h2l;
  float *costP, *sinv;
  cudaGetSymbolAddress((void**)&dh, g_dh);   cudaGetSymbolAddress((void**)&dl, g_dl);
  cudaGetSymbolAddress((void**)&w1h, g_W1h); cudaGetSymbolAddress((void**)&w1l, g_W1l);
  cudaGetSymbolAddress((void**)&w2h, g_W2h); cudaGetSymbolAddress((void**)&w2l, g_W2l);
  cudaGetSymbolAddress((void**)&w3h, g_W3h); cudaGetSymbolAddress((void**)&w3l, g_W3l);
  cudaGetSymbolAddress((void**)&h1h, g_h1h); cudaGetSymbolAddress((void**)&h1l, g_h1l);
  cudaGetSymbolAddress((void**)&h2h, g_h2h); cudaGetSymbolAddress((void**)&h2l, g_h2l);
  cudaGetSymbolAddress((void**)&costP, g_costP);
  cudaGetSymbolAddress((void**)&sinv, g_Sinv);

  // 1) Fused hi/lo bf16 splits of all inputs (4 float4 per thread)
  cvt_all<<<(CVT_Q4 + 255) / 256, 256>>>(d, W1, W2, W3, dh, dl, w1h, w1l, w2h, w2l, w3h, w3l);

  // 2) Sinv = (I + 0.5 W W^T)^-1
  setup_sinv<<<1, 1024>>>(Wm, sinv);

  const int gemm_smem = 3 * STAGE_B;  // 73728 B
  cudaFuncSetAttribute(mma_gemm<0>, cudaFuncAttributeMaxDynamicSharedMemorySize, gemm_smem);
  cudaFuncSetAttribute(mma_gemm<1>, cudaFuncAttributeMaxDynamicSharedMemorySize, gemm_smem);

  // 3-5) MLP on tensor cores; 64M x 128N tiles, 128 threads, 3 CTA/SM
  mma_gemm<0><<<dim3(HDIM / 128, BDIM / 64), 128, gemm_smem>>>(
      dh, dl, w1h, w1l, b1, nullptr, h1h, h1l, BDIM, HDIM, CDIM, CDIM);
  mma_gemm<0><<<dim3(HDIM / 128, BDIM / 64), 128, gemm_smem>>>(
      h1h, h1l, w2h, w2l, b2, nullptr, h2h, h2l, BDIM, HDIM, HDIM, HDIM);
  mma_gemm<1><<<dim3((RDIM + 127) / 128, BDIM / 64, KSPLIT), 128, gemm_smem>>>(
      h2h, h2l, w3h, w3l, nullptr, costP, nullptr, nullptr, BDIM, RDIM, HDIM, HDIM / KSPLIT);

  // 6) ADMM (persistent; over-relaxed; early exit on block convergence)
  const int admm_smem = (32 * 512 + 2 * AROWS * 512 + 4 * AROWS * 32 + 32 + KDIM * 33 + 24) * (int)sizeof(float);
  cudaFuncSetAttribute(admm_kernel, cudaFuncAttributeMaxDynamicSharedMemorySize, admm_smem);
  admm_kernel<<<BDIM / AROWS, 512, admm_smem>>>(costP, b3, Wm, cap, sinv, out);
}